// round 7
// baseline (speedup 1.0000x reference)
#include <cuda_runtime.h>

#define NN 50000
#define EE 800000
#define ET (EE + NN)

// ---------------- scratch (device globals; no allocations allowed) ----------
__device__ float g_xl[NN * 128];
__device__ float g_h[NN * 128];
__device__ float g_out[NN * 128];
__device__ float g_s[NN * 2];
__device__ float g_d[NN * 2];
__device__ int   g_emax[NN * 2];
__device__ float g_denom[NN * 2];
__device__ float g_ebuf[(size_t)ET * 2];

__device__ __forceinline__ int enc_f(float f) {
    int b = __float_as_int(f);
    return b >= 0 ? b : (b ^ 0x7FFFFFFF);
}
__device__ __forceinline__ float dec_f(int e) {
    return __int_as_float(e >= 0 ? e : (e ^ 0x7FFFFFFF));
}

// ---------------- GEMM: [N,128] @ [128,BN] -> g_xl[N,BN] --------------------
// 128xBNx16 tile, 256 threads, 8x(BN/16) per thread, float4 everywhere.
template <int BN>
__global__ void __launch_bounds__(256) gemm_kernel(const float* __restrict__ A,
                                                   const float* __restrict__ B,
                                                   int src_is_gh) {
    constexpr int BM = 128, BK = 16, TM = 8, TN = BN / 16;
    __shared__ float As[BK][BM + 4];   // k-major, padded: conflict-free
    __shared__ float Bs[BK][BN];
    const float* __restrict__ Ab = src_is_gh ? (const float*)g_h : A;
    const int tid = threadIdx.x;
    const int tx = tid & 15, ty = tid >> 4;
    const int row0 = blockIdx.x * BM;

    float acc[TM][TN];
#pragma unroll
    for (int i = 0; i < TM; i++)
#pragma unroll
        for (int j = 0; j < TN; j++) acc[i][j] = 0.f;

    for (int k0 = 0; k0 < 128; k0 += BK) {
        // A tile: 128x16 = 512 float4, 2 per thread; transpose into k-major smem
#pragma unroll
        for (int l = 0; l < 2; l++) {
            int idx = l * 256 + tid;          // 0..511
            int r = idx >> 2;                 // 0..127
            int c4 = (idx & 3) * 4;           // 0,4,8,12
            int gr = row0 + r;
            float4 v = make_float4(0.f, 0.f, 0.f, 0.f);
            if (gr < NN) v = *(const float4*)&Ab[(size_t)gr * 128 + k0 + c4];
            As[c4 + 0][r] = v.x;
            As[c4 + 1][r] = v.y;
            As[c4 + 2][r] = v.z;
            As[c4 + 3][r] = v.w;
        }
        // B tile: 16xBN floats, float4 loads
#pragma unroll
        for (int l = 0; l < (BK * BN) / (4 * 256); l++) {
            int idx = l * 256 + tid;
            int r = idx / (BN / 4);
            int c4 = (idx % (BN / 4)) * 4;
            *(float4*)&Bs[r][c4] = *(const float4*)&B[(size_t)(k0 + r) * BN + c4];
        }
        __syncthreads();
#pragma unroll
        for (int k = 0; k < BK; k++) {
            float a[TM], bb[TN];
#pragma unroll
            for (int i4 = 0; i4 < TM; i4 += 4)
                *(float4*)&a[i4] = *(const float4*)&As[k][ty * TM + i4];
#pragma unroll
            for (int j4 = 0; j4 < TN; j4 += 4)
                *(float4*)&bb[j4] = *(const float4*)&Bs[k][tx * TN + j4];
#pragma unroll
            for (int i = 0; i < TM; i++)
#pragma unroll
                for (int j = 0; j < TN; j++) acc[i][j] += a[i] * bb[j];
        }
        __syncthreads();
    }
#pragma unroll
    for (int i = 0; i < TM; i++) {
        int gr = row0 + ty * TM + i;
        if (gr < NN) {
#pragma unroll
            for (int j4 = 0; j4 < TN; j4 += 4)
                *(float4*)&g_xl[(size_t)gr * BN + tx * TN + j4] =
                    *(const float4*)&acc[i][j4];
        }
    }
}

// ---------------- per-(node,head) attention dot products --------------------
__global__ void att_kernel(const float* __restrict__ asrc,
                           const float* __restrict__ adst, int Hh) {
    int g = (blockIdx.x * blockDim.x + threadIdx.x) >> 5;
    int lane = threadIdx.x & 31;
    if (g >= NN * Hh) return;
    int node = g / Hh;
    int h = g - node * Hh;
    const float* row = g_xl + (size_t)node * Hh * 64 + h * 64;
    float v0 = row[lane], v1 = row[lane + 32];
    float vs = v0 * asrc[h * 64 + lane] + v1 * asrc[h * 64 + lane + 32];
    float vd = v0 * adst[h * 64 + lane] + v1 * adst[h * 64 + lane + 32];
#pragma unroll
    for (int o = 16; o; o >>= 1) {
        vs += __shfl_down_sync(0xFFFFFFFFu, vs, o);
        vd += __shfl_down_sync(0xFFFFFFFFu, vd, o);
    }
    if (lane == 0) {
        g_s[node * Hh + h] = vs;
        g_d[node * Hh + h] = vd;
    }
}

// ---------------- init accumulators -----------------------------------------
__global__ void init_kernel(int M) {
    int i = blockIdx.x * blockDim.x + threadIdx.x;
    if (i < NN * M) g_out[i] = 0.f;
    if (i < NN * 2) {
        g_emax[i] = (int)0x80000000;
        g_denom[i] = 0.f;
    }
}

// ---------------- edge pass 1: e = lrelu(s[src]+d[dst]); segment max --------
__global__ void edge_max_kernel(const int* __restrict__ ei, int Hh) {
    int e = blockIdx.x * blockDim.x + threadIdx.x;
    if (e >= ET) return;
    int s, d;
    if (e < EE) { s = ei[e]; d = ei[EE + e]; }
    else        { s = d = e - EE; }
#pragma unroll 2
    for (int h = 0; h < Hh; h++) {
        float v = g_s[s * Hh + h] + g_d[d * Hh + h];
        v = v > 0.f ? v : 0.2f * v;
        g_ebuf[(size_t)e * Hh + h] = v;
        atomicMax(&g_emax[d * Hh + h], enc_f(v));
    }
}

// ---------------- edge pass 2: exp + denom ----------------------------------
__global__ void edge_exp_kernel(const int* __restrict__ ei, int Hh) {
    int e = blockIdx.x * blockDim.x + threadIdx.x;
    if (e >= ET) return;
    int d;
    if (e < EE) d = ei[EE + e];
    else        d = e - EE;
#pragma unroll 2
    for (int h = 0; h < Hh; h++) {
        float m = dec_f(g_emax[d * Hh + h]);
        float ex = __expf(g_ebuf[(size_t)e * Hh + h] - m);
        g_ebuf[(size_t)e * Hh + h] = ex;
        atomicAdd(&g_denom[d * Hh + h], ex);
    }
}

// ---------------- edge pass 3: message scatter (warp per edge, float4) ------
__global__ void scatter_kernel(const int* __restrict__ ei, int Hh) {
    int g = (blockIdx.x * blockDim.x + threadIdx.x) >> 5;
    int lane = threadIdx.x & 31;
    if (g >= ET) return;
    int s, d;
    if (g < EE) { s = ei[g]; d = ei[EE + g]; }
    else        { s = d = g - EE; }
    const int M = Hh * 64;
    float a0 = g_ebuf[(size_t)g * Hh] / g_denom[d * Hh];
    float a1 = (Hh == 2) ? g_ebuf[(size_t)g * Hh + 1] / g_denom[d * Hh + 1] : 0.f;
    const float* xr = g_xl + (size_t)s * M;
    float* orow = g_out + (size_t)d * M;
    int i0 = lane * 4;                 // 4 contiguous cols per lane
    if (i0 < M) {
        float a = (i0 < 64) ? a0 : a1;
        float4 v = *(const float4*)&xr[i0];
        atomicAdd(&orow[i0 + 0], v.x * a);
        atomicAdd(&orow[i0 + 1], v.y * a);
        atomicAdd(&orow[i0 + 2], v.z * a);
        atomicAdd(&orow[i0 + 3], v.w * a);
    }
}

// ---------------- finalize: bias (+ elu); dst selected by flag --------------
__global__ void finalize_kernel(const float* __restrict__ bias,
                                float* __restrict__ outp, int M, int do_elu,
                                int dst_is_gh) {
    int i = blockIdx.x * blockDim.x + threadIdx.x;
    if (i >= NN * M) return;
    float v = g_out[i] + bias[i % M];
    if (do_elu) v = v > 0.f ? v : expm1f(v);
    if (dst_is_gh) g_h[i] = v;
    else           outp[i] = v;
}

// ---------------- host-side layer driver (kernel launches ONLY) -------------
static void run_layer(const float* in, const float* W, const float* asrc,
                      const float* adst, const float* bias, float* outp,
                      int Hh, const int* ei, int do_elu,
                      int src_is_gh, int dst_is_gh) {
    const int M = Hh * 64;
    if (M == 128)
        gemm_kernel<128><<<(NN + 127) / 128, 256>>>(in, W, src_is_gh);
    else
        gemm_kernel<64><<<(NN + 127) / 128, 256>>>(in, W, src_is_gh);

    int warps = NN * Hh;
    att_kernel<<<(warps * 32 + 255) / 256, 256>>>(asrc, adst, Hh);

    init_kernel<<<(NN * M + 255) / 256, 256>>>(M);
    edge_max_kernel<<<(ET + 255) / 256, 256>>>(ei, Hh);
    edge_exp_kernel<<<(ET + 255) / 256, 256>>>(ei, Hh);
    scatter_kernel<<<(ET * 32 + 255) / 256, 256>>>(ei, Hh);
    finalize_kernel<<<(NN * M + 255) / 256, 256>>>(bias, outp, M, do_elu,
                                                   dst_is_gh);
}

extern "C" void kernel_launch(void* const* d_in, const int* in_sizes, int n_in,
                              void* d_out, int out_size) {
    const float* x   = (const float*)d_in[0];
    const int*   ei  = (const int*)d_in[1];   // int64 in reference -> int32 here
    const float* W0  = (const float*)d_in[2];
    const float* as0 = (const float*)d_in[3];
    const float* ad0 = (const float*)d_in[4];
    const float* b0  = (const float*)d_in[5];
    const float* W1  = (const float*)d_in[6];
    const float* as1 = (const float*)d_in[7];
    const float* ad1 = (const float*)d_in[8];
    const float* b1  = (const float*)d_in[9];
    const float* W2  = (const float*)d_in[10];
    const float* as2 = (const float*)d_in[11];
    const float* ad2 = (const float*)d_in[12];
    const float* b2  = (const float*)d_in[13];

    run_layer(x, W0, as0, ad0, b0, nullptr,        2, ei, 1, 0, 1);
    run_layer(x, W1, as1, ad1, b1, nullptr,        2, ei, 1, 1, 1);
    run_layer(x, W2, as2, ad2, b2, (float*)d_out,  1, ei, 0, 1, 0);
}

// round 8
// speedup vs baseline: 2.7864x; 2.7864x over previous
#include <cuda_runtime.h>

#define NN 50000
#define EE 800000
#define ET (EE + NN)

// ---------------- scratch (device globals; no allocations allowed) ----------
__device__ float g_xl[NN * 128];     // transformed features [N, M]
__device__ float g_h[NN * 128];      // inter-layer activations
__device__ float g_s[NN * 2];        // alpha_src per (node, head)
__device__ float g_d[NN * 2];        // alpha_dst per (node, head)
__device__ int   g_rowptr[NN + 1];   // CSR row pointers (by dst)
__device__ int   g_cnt[NN];          // degree counts / fill cursors
__device__ int   g_src[ET];          // CSR: src node per incoming edge

// ---------------- GEMM: [N,128] @ [128,BN] -> g_xl[N,BN] --------------------
template <int BN>
__global__ void __launch_bounds__(256) gemm_kernel(const float* __restrict__ A,
                                                   const float* __restrict__ B,
                                                   int src_is_gh) {
    constexpr int BM = 128, BK = 16, TM = 8, TN = BN / 16;
    __shared__ float As[BK][BM + 4];
    __shared__ float Bs[BK][BN];
    const float* __restrict__ Ab = src_is_gh ? (const float*)g_h : A;
    const int tid = threadIdx.x;
    const int tx = tid & 15, ty = tid >> 4;
    const int row0 = blockIdx.x * BM;

    float acc[TM][TN];
#pragma unroll
    for (int i = 0; i < TM; i++)
#pragma unroll
        for (int j = 0; j < TN; j++) acc[i][j] = 0.f;

    for (int k0 = 0; k0 < 128; k0 += BK) {
#pragma unroll
        for (int l = 0; l < 2; l++) {
            int idx = l * 256 + tid;
            int r = idx >> 2;
            int c4 = (idx & 3) * 4;
            int gr = row0 + r;
            float4 v = make_float4(0.f, 0.f, 0.f, 0.f);
            if (gr < NN) v = *(const float4*)&Ab[(size_t)gr * 128 + k0 + c4];
            As[c4 + 0][r] = v.x;
            As[c4 + 1][r] = v.y;
            As[c4 + 2][r] = v.z;
            As[c4 + 3][r] = v.w;
        }
#pragma unroll
        for (int l = 0; l < (BK * BN) / (4 * 256); l++) {
            int idx = l * 256 + tid;
            int r = idx / (BN / 4);
            int c4 = (idx % (BN / 4)) * 4;
            *(float4*)&Bs[r][c4] = *(const float4*)&B[(size_t)(k0 + r) * BN + c4];
        }
        __syncthreads();
#pragma unroll
        for (int k = 0; k < BK; k++) {
            float a[TM], bb[TN];
#pragma unroll
            for (int i4 = 0; i4 < TM; i4 += 4)
                *(float4*)&a[i4] = *(const float4*)&As[k][ty * TM + i4];
#pragma unroll
            for (int j4 = 0; j4 < TN; j4 += 4)
                *(float4*)&bb[j4] = *(const float4*)&Bs[k][tx * TN + j4];
#pragma unroll
            for (int i = 0; i < TM; i++)
#pragma unroll
                for (int j = 0; j < TN; j++) acc[i][j] += a[i] * bb[j];
        }
        __syncthreads();
    }
#pragma unroll
    for (int i = 0; i < TM; i++) {
        int gr = row0 + ty * TM + i;
        if (gr < NN) {
#pragma unroll
            for (int j4 = 0; j4 < TN; j4 += 4)
                *(float4*)&g_xl[(size_t)gr * BN + tx * TN + j4] =
                    *(const float4*)&acc[i][j4];
        }
    }
}

// ---------------- per-(node,head) attention dot products --------------------
__global__ void att_kernel(const float* __restrict__ asrc,
                           const float* __restrict__ adst, int Hh) {
    int g = (blockIdx.x * blockDim.x + threadIdx.x) >> 5;
    int lane = threadIdx.x & 31;
    if (g >= NN * Hh) return;
    int node = g / Hh;
    int h = g - node * Hh;
    const float* row = g_xl + (size_t)node * Hh * 64 + h * 64;
    float v0 = row[lane], v1 = row[lane + 32];
    float vs = v0 * asrc[h * 64 + lane] + v1 * asrc[h * 64 + lane + 32];
    float vd = v0 * adst[h * 64 + lane] + v1 * adst[h * 64 + lane + 32];
#pragma unroll
    for (int o = 16; o; o >>= 1) {
        vs += __shfl_down_sync(0xFFFFFFFFu, vs, o);
        vd += __shfl_down_sync(0xFFFFFFFFu, vd, o);
    }
    if (lane == 0) {
        g_s[node * Hh + h] = vs;
        g_d[node * Hh + h] = vd;
    }
}

// ---------------- CSR build (once per launch) -------------------------------
__global__ void zero_cnt_kernel() {
    int i = blockIdx.x * blockDim.x + threadIdx.x;
    if (i < NN) g_cnt[i] = 0;
}

__global__ void count_kernel(const int* __restrict__ ei) {
    int e = blockIdx.x * blockDim.x + threadIdx.x;
    if (e >= ET) return;
    int d = (e < EE) ? ei[EE + e] : e - EE;
    atomicAdd(&g_cnt[d], 1);
}

__global__ void scan_kernel() {
    __shared__ int ps[1024];
    const int t = threadIdx.x;
    const int CH = (NN + 1023) / 1024;  // 49
    int base = t * CH;
    int sum = 0;
    for (int i = 0; i < CH; i++) {
        int idx = base + i;
        if (idx < NN) sum += g_cnt[idx];
    }
    ps[t] = sum;
    __syncthreads();
    for (int off = 1; off < 1024; off <<= 1) {
        int v = (t >= off) ? ps[t - off] : 0;
        __syncthreads();
        ps[t] += v;
        __syncthreads();
    }
    int run = (t == 0) ? 0 : ps[t - 1];
    for (int i = 0; i < CH; i++) {
        int idx = base + i;
        if (idx < NN) {
            g_rowptr[idx] = run;
            run += g_cnt[idx];
        }
    }
    if (t == 1023) g_rowptr[NN] = run;
}

__global__ void fill_kernel(const int* __restrict__ ei) {
    int e = blockIdx.x * blockDim.x + threadIdx.x;
    if (e >= ET) return;
    int s, d;
    if (e < EE) { s = ei[e]; d = ei[EE + e]; }
    else        { s = d = e - EE; }
    int pos = g_rowptr[d] + atomicAdd(&g_cnt[d], 1);
    g_src[pos] = s;
}

// ---------------- fused softmax + aggregate + bias + elu --------------------
// One warp per dst node. M = Hh*64 (128 or 64).
template <int M>
__global__ void __launch_bounds__(256) agg_kernel(const float* __restrict__ bias,
                                                  float* __restrict__ outp,
                                                  int do_elu, int dst_is_gh) {
    constexpr int Hh = M / 64;
    constexpr int VEC = M / 32;  // floats per lane: 4 (M=128) or 2 (M=64)
    __shared__ float sh_ex[8][Hh][32];
    __shared__ int   sh_s[8][32];
    const int w = threadIdx.x >> 5, lane = threadIdx.x & 31;
    const int node = blockIdx.x * 8 + w;
    if (node >= NN) return;
    const int start = g_rowptr[node], end = g_rowptr[node + 1];
    const int h = (Hh == 2) ? (lane >> 4) : 0;

    const float d0 = g_d[node * Hh + 0];
    const float d1 = (Hh == 2) ? g_d[node * Hh + 1] : 0.f;

    // pass 1: per-head max over incoming edges (strided)
    float m0 = -3.4e38f, m1 = -3.4e38f;
    for (int e = start + lane; e < end; e += 32) {
        int s = g_src[e];
        float v0 = g_s[s * Hh + 0] + d0;
        v0 = v0 > 0.f ? v0 : 0.2f * v0;
        m0 = fmaxf(m0, v0);
        if (Hh == 2) {
            float v1 = g_s[s * Hh + 1] + d1;
            v1 = v1 > 0.f ? v1 : 0.2f * v1;
            m1 = fmaxf(m1, v1);
        }
    }
#pragma unroll
    for (int o = 16; o; o >>= 1) {
        m0 = fmaxf(m0, __shfl_xor_sync(0xFFFFFFFFu, m0, o));
        if (Hh == 2) m1 = fmaxf(m1, __shfl_xor_sync(0xFFFFFFFFu, m1, o));
    }

    // pass 2: chunked exp + feature gather
    float acc[VEC];
#pragma unroll
    for (int k = 0; k < VEC; k++) acc[k] = 0.f;
    float denom = 0.f;

    for (int c0 = start; c0 < end; c0 += 32) {
        int n = min(32, end - c0);
        if (lane < n) {
            int s = g_src[c0 + lane];
            sh_s[w][lane] = s;
            float v0 = g_s[s * Hh + 0] + d0;
            v0 = v0 > 0.f ? v0 : 0.2f * v0;
            sh_ex[w][0][lane] = __expf(v0 - m0);
            if (Hh == 2) {
                float v1 = g_s[s * Hh + 1] + d1;
                v1 = v1 > 0.f ? v1 : 0.2f * v1;
                sh_ex[w][1][lane] = __expf(v1 - m1);
            }
        }
        __syncwarp();
#pragma unroll 4
        for (int j = 0; j < n; j++) {
            int s = sh_s[w][j];
            float ex = sh_ex[w][h][j];
            denom += ex;
            const float* xr = &g_xl[(size_t)s * M + lane * VEC];
            if (VEC == 4) {
                float4 xv = *(const float4*)xr;
                acc[0] += ex * xv.x;
                acc[1] += ex * xv.y;
                acc[2] += ex * xv.z;
                acc[3] += ex * xv.w;
            } else {
                float2 xv = *(const float2*)xr;
                acc[0] += ex * xv.x;
                acc[1] += ex * xv.y;
            }
        }
        __syncwarp();
    }

    float inv = 1.f / denom;
    float* dst = dst_is_gh ? (float*)g_h : outp;
    int col = lane * VEC;
#pragma unroll
    for (int k = 0; k < VEC; k++) {
        float v = acc[k] * inv + bias[col + k];
        if (do_elu) v = v > 0.f ? v : expm1f(v);
        dst[(size_t)node * M + col + k] = v;
    }
}

// ---------------- host-side driver (kernel launches ONLY) -------------------
static void run_layer(const float* in, const float* W, const float* asrc,
                      const float* adst, const float* bias, float* outp,
                      int Hh, int do_elu, int src_is_gh, int dst_is_gh) {
    const int M = Hh * 64;
    if (M == 128)
        gemm_kernel<128><<<(NN + 127) / 128, 256>>>(in, W, src_is_gh);
    else
        gemm_kernel<64><<<(NN + 127) / 128, 256>>>(in, W, src_is_gh);

    int warps = NN * Hh;
    att_kernel<<<(warps * 32 + 255) / 256, 256>>>(asrc, adst, Hh);

    if (M == 128)
        agg_kernel<128><<<(NN + 7) / 8, 256>>>(bias, outp, do_elu, dst_is_gh);
    else
        agg_kernel<64><<<(NN + 7) / 8, 256>>>(bias, outp, do_elu, dst_is_gh);
}

extern "C" void kernel_launch(void* const* d_in, const int* in_sizes, int n_in,
                              void* d_out, int out_size) {
    const float* x   = (const float*)d_in[0];
    const int*   ei  = (const int*)d_in[1];   // int64 in reference -> int32 here
    const float* W0  = (const float*)d_in[2];
    const float* as0 = (const float*)d_in[3];
    const float* ad0 = (const float*)d_in[4];
    const float* b0  = (const float*)d_in[5];
    const float* W1  = (const float*)d_in[6];
    const float* as1 = (const float*)d_in[7];
    const float* ad1 = (const float*)d_in[8];
    const float* b1  = (const float*)d_in[9];
    const float* W2  = (const float*)d_in[10];
    const float* as2 = (const float*)d_in[11];
    const float* ad2 = (const float*)d_in[12];
    const float* b2  = (const float*)d_in[13];

    // CSR by dst (edge structure shared by all 3 layers)
    zero_cnt_kernel<<<(NN + 255) / 256, 256>>>();
    count_kernel<<<(ET + 255) / 256, 256>>>(ei);
    scan_kernel<<<1, 1024>>>();
    zero_cnt_kernel<<<(NN + 255) / 256, 256>>>();
    fill_kernel<<<(ET + 255) / 256, 256>>>(ei);

    run_layer(x, W0, as0, ad0, b0, nullptr,       2, 1, 0, 1);
    run_layer(x, W1, as1, ad1, b1, nullptr,       2, 1, 1, 1);
    run_layer(x, W2, as2, ad2, b2, (float*)d_out, 1, 0, 1, 0);
}